// round 8
// baseline (speedup 1.0000x reference)
#include <cuda_runtime.h>
#include <math.h>

// Problem constants
#define HW    4096
#define Bn    8
#define Tn    50
#define CIN   32

typedef unsigned long long u64;

// Scratch (static __device__ arrays — allocation-free per harness rules)
__device__ float g_XC[400u * 128u * 4096u];   // [t*8+b][128][4096]  x-conv precompute
__device__ float g_yconv[8 * 96 * 4096];       // per-step conv(Y, Wy)
__device__ float g_Y[8 * 32 * 4096];
__device__ float g_Z[8 * 32 * 4096];
__device__ float g_G2[8 * 32 * 4096];          // sigmoid(xg2 + yg2) for current step

__device__ __forceinline__ float fsigmoid(float x) {
    return 1.0f / (1.0f + __expf(-x));
}
__device__ __forceinline__ float ftanh(float x) {
    x = fminf(fmaxf(x, -12.0f), 12.0f);
    float e = __expf(2.0f * x);
    return 1.0f - 2.0f / (e + 1.0f);
}

// ---- packed fp32x2 helpers (Blackwell FFMA2 path; ptxas never auto-fuses) ----
__device__ __forceinline__ u64 pk2(float lo, float hi) {
    u64 r; asm("mov.b64 %0, {%1, %2};" : "=l"(r) : "f"(lo), "f"(hi)); return r;
}
__device__ __forceinline__ void upk2(u64 v, float& lo, float& hi) {
    asm("mov.b64 {%0, %1}, %2;" : "=f"(lo), "=f"(hi) : "l"(v));
}
__device__ __forceinline__ void fma2(u64& d, u64 a, u64 b) {
    asm("fma.rn.f32x2 %0, %1, %2, %3;" : "=l"(d) : "l"(a), "l"(b), "l"(d));
}

// ---------------------------------------------------------------------------
// 3x3 SAME conv, Cin=32, 8 output channels per block, f32x2 packed math.
// Block: 128 threads = 64 spatial (8x8 of 4x4 patches => 32x32 tile)
//        x 2 channel subgroups (4 ch each). Each thread: 4ch x 4x4 patch,
//        held as 32 packed f32x2 accumulators (x-adjacent pairs).
// MODE 0: in = X (all t,b images), out -> g_XC          (grid.z = 400)
// MODE 1: in = g_Y,               out -> g_yconv        (grid.z = 8)
// MODE 2: in = g_Z,  epilogue fuses Y update + output store (grid.z = 8)
// ---------------------------------------------------------------------------
template<int MODE>
__global__ void __launch_bounds__(128)
conv3x3_k(const float* __restrict__ xin,
          const float* __restrict__ wts,
          const float* __restrict__ bias,
          float* __restrict__ out,
          int t)
{
    __shared__ float sIn[8][34 * 34];   // 8 input channels of the (32+2)^2 halo tile
    __shared__ float sW[8][8][9];       // [ci][co][tap]

    const int tid  = threadIdx.x;
    const int tile = blockIdx.x;               // 0..3
    const int h0   = (tile >> 1) * 32;
    const int w0   = (tile & 1) * 32;
    const int cog  = blockIdx.y;               // output channel group (8 ch)
    const int img  = blockIdx.z;

    int b, ti;
    if (MODE == 0) { b = img & 7; ti = img >> 3; }
    else           { b = img;     ti = t; }

    size_t in_base; int chs;
    const float* src;
    if (MODE == 0) { src = xin;  in_base = ((size_t)b * CIN * Tn + ti) * HW; chs = Tn * HW; }
    else if (MODE == 1) { src = g_Y; in_base = (size_t)b * CIN * HW; chs = HW; }
    else { src = g_Z; in_base = (size_t)b * CIN * HW; chs = HW; }

    const int sp    = tid & 63;
    const int cosub = tid >> 6;               // 0 or 1
    const int py    = (sp >> 3) << 2;          // patch origin y in [0,32)
    const int px    = (sp & 7) << 2;           // patch origin x in [0,32)

    // acc2[co][iy][pr]: pr=0 -> ix{0,1}, pr=1 -> ix{2,3}
    u64 acc2[4][4][2];
#pragma unroll
    for (int c = 0; c < 4; c++)
#pragma unroll
        for (int iy = 0; iy < 4; iy++) {
            acc2[c][iy][0] = 0ull; acc2[c][iy][1] = 0ull;
        }

    for (int ci0 = 0; ci0 < CIN; ci0 += 8) {
        // --- stage input halo tile (zero-padded SAME borders) ---
        for (int e = tid; e < 8 * 34 * 34; e += 128) {
            int ci = e / (34 * 34);
            int r  = e - ci * (34 * 34);
            int y  = r / 34;
            int x  = r - y * 34;
            int gy = h0 - 1 + y;
            int gx = w0 - 1 + x;
            float v = 0.0f;
            if ((unsigned)gy < 64u && (unsigned)gx < 64u)
                v = src[in_base + (size_t)(ci0 + ci) * chs + gy * 64 + gx];
            sIn[ci][r] = v;
        }
        // --- stage weights ---
        for (int e = tid; e < 8 * 8 * 9; e += 128) {
            int ci  = e / 72;
            int r   = e - ci * 72;
            int co  = r / 9;
            int tap = r - co * 9;
            sW[ci][co][tap] = wts[((size_t)(cog * 8 + co) * CIN + ci0 + ci) * 9 + tap];
        }
        __syncthreads();

#pragma unroll 1
        for (int ci = 0; ci < 8; ci++) {
            // 6x6 input patch -> sliding-window x-pairs p[row][j] = (v[j], v[j+1])
            float rv[36];
#pragma unroll
            for (int yy = 0; yy < 6; yy++)
#pragma unroll
                for (int xx = 0; xx < 6; xx++)
                    rv[yy * 6 + xx] = sIn[ci][(py + yy) * 34 + px + xx];
            u64 p[6][5];
#pragma unroll
            for (int r = 0; r < 6; r++)
#pragma unroll
                for (int j = 0; j < 5; j++)
                    p[r][j] = pk2(rv[r * 6 + j], rv[r * 6 + j + 1]);

#pragma unroll
            for (int co = 0; co < 4; co++) {
                u64 wp[9];
#pragma unroll
                for (int tp = 0; tp < 9; tp++) {
                    float w = sW[ci][cosub * 4 + co][tp];
                    wp[tp] = pk2(w, w);
                }
#pragma unroll
                for (int dy = 0; dy < 3; dy++)
#pragma unroll
                    for (int dx = 0; dx < 3; dx++)
#pragma unroll
                        for (int iy = 0; iy < 4; iy++) {
                            fma2(acc2[co][iy][0], p[iy + dy][dx],     wp[dy * 3 + dx]);
                            fma2(acc2[co][iy][1], p[iy + dy][dx + 2], wp[dy * 3 + dx]);
                        }
            }
        }
        __syncthreads();
    }

    // --- epilogue ---
#pragma unroll
    for (int co = 0; co < 4; co++) {
        int c = cog * 8 + cosub * 4 + co;
        float bv = bias[c];
#pragma unroll
        for (int iy = 0; iy < 4; iy++) {
            float a[4];
            upk2(acc2[co][iy][0], a[0], a[1]);
            upk2(acc2[co][iy][1], a[2], a[3]);
#pragma unroll
            for (int ix = 0; ix < 4; ix++) {
                int pos = (h0 + py + iy) * 64 + (w0 + px + ix);
                float v = a[ix] + bv;
                if (MODE == 0) {
                    g_XC[((size_t)img * 128 + c) * HW + pos] = v;
                } else if (MODE == 1) {
                    g_yconv[((size_t)b * 96 + c) * HW + pos] = v;
                } else {
                    size_t off = ((size_t)b * 32 + c) * HW + pos;
                    float g2 = g_G2[off];
                    float xy = g_XC[(((size_t)(t * 8 + b)) * 128 + 96 + c) * HW + pos];
                    float yv = g_Y[off];
                    float yn = fmaf(g2, ftanh(xy + v) - yv, yv);   // (1-g2)*Y + g2*tanh
                    g_Y[off] = yn;
                    out[((size_t)(b * 32 + c) * Tn + t) * HW + pos] = yn;
                }
            }
        }
    }
}

// ---------------------------------------------------------------------------
// Elementwise (float4): ms1 gate, Z update, precompute G2 gate for Y update.
// ---------------------------------------------------------------------------
__global__ void elemZ_k(int t)
{
    int i4 = blockIdx.x * blockDim.x + threadIdx.x;    // over 1M/4 float4s
    if (i4 >= (8 * 32 * 4096) / 4) return;
    int b   = i4 >> 15;             // / (32*1024)
    int rem = i4 & 32767;
    int c   = rem >> 10;
    int p4  = rem & 1023;

    const float4* yc = (const float4*)g_yconv + ((size_t)b * 96 + c) * (HW / 4) + p4;
    const float4* xc = (const float4*)g_XC + (((size_t)(t * 8 + b)) * 128 + c) * (HW / 4) + p4;
    float4 yc1 = yc[0];
    float4 yc2 = yc[32 * HW / 4];
    float4 yc3 = yc[64 * HW / 4];
    float4 x1  = xc[0];
    float4 x2  = xc[32 * HW / 4];
    float4 x3  = xc[64 * HW / 4];

    float4 zv = ((const float4*)g_Z)[i4];
    float4 zn, g2;
#pragma unroll
    for (int k = 0; k < 4; k++) {
        float a1 = ((&x1.x)[k]) + ((&yc1.x)[k]);
        float a2 = ((&x2.x)[k]) + ((&yc2.x)[k]);
        float az = ((&x3.x)[k]) + ((&yc3.x)[k]);
        float ms1 = fsigmoid(a1);
        float z0  = (&zv.x)[k];
        (&zn.x)[k] = fmaf(ms1, ftanh(az) - z0, z0);
        (&g2.x)[k] = fsigmoid(a2);
    }
    ((float4*)g_Z)[i4]  = zn;
    ((float4*)g_G2)[i4] = g2;
}

__global__ void init_k()
{
    int idx = blockIdx.x * blockDim.x + threadIdx.x;
    if (idx < 8 * 32 * 4096) { g_Y[idx] = 0.0f; g_Z[idx] = 0.0f; }
}

extern "C" void kernel_launch(void* const* d_in, const int* in_sizes, int n_in,
                              void* d_out, int out_size)
{
    const float* X  = (const float*)d_in[0];
    const float* Wx = (const float*)d_in[1];
    const float* bx = (const float*)d_in[2];
    const float* Wy = (const float*)d_in[3];
    const float* by = (const float*)d_in[4];
    const float* Wz = (const float*)d_in[5];
    const float* bz = (const float*)d_in[6];
    float* out = (float*)d_out;

    // Reset recurrent state (graph is replayed; must be deterministic).
    init_k<<<(8 * 32 * 4096 + 255) / 256, 256>>>();

    // Precompute all input convolutions (400 independent images, 128 out ch).
    conv3x3_k<0><<<dim3(4, 16, 400), 128>>>(X, Wx, bx, nullptr, 0);

    // Recurrence: 50 steps, 3 launches each.
    for (int t = 0; t < Tn; t++) {
        conv3x3_k<1><<<dim3(4, 12, 8), 128>>>(nullptr, Wy, by, nullptr, t);
        elemZ_k<<<((8 * 32 * 4096) / 4 + 255) / 256, 256>>>(t);
        conv3x3_k<2><<<dim3(4, 4, 8), 128>>>(nullptr, Wz, bz, out, t);
    }
}

// round 11
// speedup vs baseline: 2.4171x; 2.4171x over previous
#include <cuda_runtime.h>
#include <cuda_bf16.h>
#include <cstdint>
#include <math.h>

#define HW 4096
#define Tn 50

typedef uint32_t u32;
typedef unsigned short u16;

// Scratch (static __device__ arrays — allocation-free per harness rules)
__device__ float g_XC[400u * 128u * 4096u];   // [t*8+b][128][4096]
__device__ float g_yconv[8 * 96 * 4096];
__device__ float g_Y[8 * 32 * 4096];
__device__ float g_Z[8 * 32 * 4096];
__device__ float g_G2[8 * 32 * 4096];

__device__ __forceinline__ float fsigmoid(float x) {
    return 1.0f / (1.0f + __expf(-x));
}
__device__ __forceinline__ float ftanh(float x) {
    x = fminf(fmaxf(x, -12.0f), 12.0f);
    float e = __expf(2.0f * x);
    return 1.0f - 2.0f / (e + 1.0f);
}

// mma.sync m16n8k16 bf16 (baseline PTX, sm_80+; runs on tensor pipe)
__device__ __forceinline__ void mma16816(float* d,
                                         u32 a0, u32 a1, u32 a2, u32 a3,
                                         u32 b0, u32 b1) {
    asm volatile(
        "mma.sync.aligned.m16n8k16.row.col.f32.bf16.bf16.f32 "
        "{%0,%1,%2,%3}, {%4,%5,%6,%7}, {%8,%9}, {%0,%1,%2,%3};"
        : "+f"(d[0]), "+f"(d[1]), "+f"(d[2]), "+f"(d[3])
        : "r"(a0), "r"(a1), "r"(a2), "r"(a3), "r"(b0), "r"(b1));
}

// ---------------------------------------------------------------------------
// Shared-memory layout (dynamic):
//   sAh / sAl : halo tile, channel-major [6 rows][66 x][40 ci-pad] bf16
//   sWh / sWl : weights [32 co][296 kpad] bf16, k = tap*32 + ci
//   sBias     : 32 floats
// ---------------------------------------------------------------------------
#define CIPAD   40
#define AELEMS  (6 * 66 * CIPAD)       // 15840
#define KPAD    296
#define WELEMS  (32 * KPAD)            // 9472
#define OFF_AH  0
#define OFF_AL  (AELEMS * 2)                     // 31680
#define OFF_WH  (OFF_AL + AELEMS * 2)            // 63360
#define OFF_WL  (OFF_WH + WELEMS * 2)            // 82304
#define OFF_BI  (OFF_WL + WELEMS * 2)            // 101248
#define SMEM_SZ (OFF_BI + 128)                   // 101376

// ---------------------------------------------------------------------------
// Tensor-core 3x3 SAME conv, Cin=32, 32 output channels per CTA.
// CTA: 256 thr = 8 warps; CTA tile M=256 pixels (4 rows x 64), warp M=32,N=32.
// K = 288 (9 taps x 32 ci) via m16n8k16, 3-term bf16 hi/lo split.
// MODE 0: X -> g_XC (128 co via blockIdx.y=0..3, grid.z=400 images)
// MODE 1: g_Y -> g_yconv (96 co, blockIdx.y=0..2, grid.z=8)
// MODE 2: g_Z -> fused Y update -> g_Y and out (32 co, grid.z=8)
// ---------------------------------------------------------------------------
template<int MODE>
__global__ void __launch_bounds__(256, 2)
conv_tc(const float* __restrict__ X,
        const float* __restrict__ wts,
        const float* __restrict__ bias,
        float* __restrict__ out,
        int t)
{
    extern __shared__ char smem[];
    u16*   sAh   = (u16*)(smem + OFF_AH);
    u16*   sAl   = (u16*)(smem + OFF_AL);
    u16*   sWh   = (u16*)(smem + OFF_WH);
    u16*   sWl   = (u16*)(smem + OFF_WL);
    float* sBias = (float*)(smem + OFF_BI);

    const int tid   = threadIdx.x;
    const int ytile = blockIdx.x;        // 0..15 (4 image rows each)
    const int cog   = blockIdx.y;        // group of 32 output channels
    const int img   = blockIdx.z;

    int b, ti;
    if (MODE == 0) { b = img & 7; ti = img >> 3; }
    else           { b = img;     ti = t; }

    const float* src;
    size_t in_base; int chstride;
    if (MODE == 0)      { src = X;   in_base = ((size_t)b * 32 * Tn + ti) * HW; chstride = Tn * HW; }
    else if (MODE == 1) { src = g_Y; in_base = (size_t)b * 32 * HW; chstride = HW; }
    else                { src = g_Z; in_base = (size_t)b * 32 * HW; chstride = HW; }

    const int y0 = ytile * 4;

    // ---- stage weights: k = tap*32 + ci, hi/lo split ----
    for (int e = tid; e < 32 * 288; e += 256) {
        int co = e / 288, k = e - co * 288;
        int tap = k >> 5, ci = k & 31;
        float w = wts[((size_t)(cog * 32 + co) * 32 + ci) * 9 + tap];
        __nv_bfloat16 wh = __float2bfloat16(w);
        __nv_bfloat16 wl = __float2bfloat16(w - __bfloat162float(wh));
        sWh[co * KPAD + k] = __bfloat16_as_ushort(wh);
        sWl[co * KPAD + k] = __bfloat16_as_ushort(wl);
    }
    if (tid < 32) sBias[tid] = bias[cog * 32 + tid];

    // ---- stage halo tile [6][66][ci] channel-major, SAME zero-padding ----
    for (int e = tid; e < 32 * 6 * 66; e += 256) {
        int ci = e / 396, r = e - ci * 396;
        int hy = r / 66,  hx = r - hy * 66;
        int gy = y0 - 1 + hy, gx = hx - 1;
        float v = 0.0f;
        if ((unsigned)gy < 64u && (unsigned)gx < 64u)
            v = src[in_base + (size_t)ci * chstride + gy * 64 + gx];
        __nv_bfloat16 h = __float2bfloat16(v);
        __nv_bfloat16 l = __float2bfloat16(v - __bfloat162float(h));
        int slot = (hy * 66 + hx) * CIPAD + ci;
        sAh[slot] = __bfloat16_as_ushort(h);
        sAl[slot] = __bfloat16_as_ushort(l);
    }
    __syncthreads();

    // ---- warp GEMM: M=32, N=32 ----
    const int wid  = tid >> 5;
    const int lane = tid & 31;
    const int gid  = lane >> 2;        // 0..7
    const int tig  = lane & 3;         // 0..3
    const int m0   = wid * 32;

    // A-row base element offsets (4 rows: mf*16 + gid + {0,8})
    int abase[4];
#pragma unroll
    for (int r = 0; r < 4; r++) {
        int m  = m0 + r * 8 + gid;
        int py = m >> 6, px = m & 63;
        abase[r] = (py * 66 + px) * CIPAD + tig * 2;
    }
    // B base element offsets per n-frag
    int bbase[4];
#pragma unroll
    for (int nf = 0; nf < 4; nf++)
        bbase[nf] = (nf * 8 + gid) * KPAD + tig * 2;

    float acc[2][4][4];
#pragma unroll
    for (int mf = 0; mf < 2; mf++)
#pragma unroll
        for (int nf = 0; nf < 4; nf++)
#pragma unroll
            for (int i = 0; i < 4; i++) acc[mf][nf][i] = 0.0f;

#pragma unroll 1
    for (int tap = 0; tap < 9; tap++) {
        const int dy = tap / 3, dx = tap - dy * 3;
        const int aofs_t = (dy * 66 + dx) * CIPAD;
        const int bofs_t = tap * 32;
#pragma unroll
        for (int kc = 0; kc < 2; kc++) {
            const int aofs = aofs_t + kc * 16;
            const int bofs = bofs_t + kc * 16;

            u32 Ah[2][4], Al[2][4];
#pragma unroll
            for (int mf = 0; mf < 2; mf++) {
                int i0 = abase[2 * mf]     + aofs;
                int i1 = abase[2 * mf + 1] + aofs;
                Ah[mf][0] = *(const u32*)&sAh[i0];
                Ah[mf][1] = *(const u32*)&sAh[i1];
                Ah[mf][2] = *(const u32*)&sAh[i0 + 8];
                Ah[mf][3] = *(const u32*)&sAh[i1 + 8];
                Al[mf][0] = *(const u32*)&sAl[i0];
                Al[mf][1] = *(const u32*)&sAl[i1];
                Al[mf][2] = *(const u32*)&sAl[i0 + 8];
                Al[mf][3] = *(const u32*)&sAl[i1 + 8];
            }
            u32 Bh[4][2], Bl[4][2];
#pragma unroll
            for (int nf = 0; nf < 4; nf++) {
                int j = bbase[nf] + bofs;
                Bh[nf][0] = *(const u32*)&sWh[j];
                Bh[nf][1] = *(const u32*)&sWh[j + 8];
                Bl[nf][0] = *(const u32*)&sWl[j];
                Bl[nf][1] = *(const u32*)&sWl[j + 8];
            }
#pragma unroll
            for (int mf = 0; mf < 2; mf++)
#pragma unroll
                for (int nf = 0; nf < 4; nf++) {
                    mma16816(acc[mf][nf], Ah[mf][0], Ah[mf][1], Ah[mf][2], Ah[mf][3],
                             Bh[nf][0], Bh[nf][1]);
                    mma16816(acc[mf][nf], Al[mf][0], Al[mf][1], Al[mf][2], Al[mf][3],
                             Bh[nf][0], Bh[nf][1]);
                    mma16816(acc[mf][nf], Ah[mf][0], Ah[mf][1], Ah[mf][2], Ah[mf][3],
                             Bl[nf][0], Bl[nf][1]);
                }
        }
    }

    // ---- epilogue: D[m][n] -> global ----
#pragma unroll
    for (int mf = 0; mf < 2; mf++) {
#pragma unroll
        for (int nf = 0; nf < 4; nf++) {
#pragma unroll
            for (int i = 0; i < 4; i++) {
                int m   = m0 + mf * 16 + gid + (i >> 1) * 8;
                int n   = nf * 8 + tig * 2 + (i & 1);
                int pix = ytile * 256 + m;          // global pixel index
                int co  = cog * 32 + n;
                float v = acc[mf][nf][i] + sBias[n];
                if (MODE == 0) {
                    g_XC[((size_t)img * 128 + co) * HW + pix] = v;
                } else if (MODE == 1) {
                    g_yconv[((size_t)b * 96 + co) * HW + pix] = v;
                } else {
                    size_t off = ((size_t)b * 32 + co) * HW + pix;
                    float g2 = g_G2[off];
                    float xy = g_XC[(((size_t)(t * 8 + b)) * 128 + 96 + co) * HW + pix];
                    float yv = g_Y[off];
                    float yn = fmaf(g2, ftanh(xy + v) - yv, yv);
                    g_Y[off] = yn;
                    out[((size_t)(b * 32 + co) * Tn + t) * HW + pix] = yn;
                }
            }
        }
    }
}

// ---------------------------------------------------------------------------
// Elementwise (float4): ms1 gate, Z update, precompute G2 gate for Y update.
// ---------------------------------------------------------------------------
__global__ void elemZ_k(int t)
{
    int i4 = blockIdx.x * blockDim.x + threadIdx.x;
    if (i4 >= (8 * 32 * 4096) / 4) return;
    int b   = i4 >> 15;
    int rem = i4 & 32767;
    int c   = rem >> 10;
    int p4  = rem & 1023;

    const float4* yc = (const float4*)g_yconv + ((size_t)b * 96 + c) * (HW / 4) + p4;
    const float4* xc = (const float4*)g_XC + (((size_t)(t * 8 + b)) * 128 + c) * (HW / 4) + p4;
    float4 yc1 = yc[0];
    float4 yc2 = yc[32 * HW / 4];
    float4 yc3 = yc[64 * HW / 4];
    float4 x1  = xc[0];
    float4 x2  = xc[32 * HW / 4];
    float4 x3  = xc[64 * HW / 4];

    float4 zv = ((const float4*)g_Z)[i4];
    float4 zn, g2;
#pragma unroll
    for (int k = 0; k < 4; k++) {
        float a1 = ((&x1.x)[k]) + ((&yc1.x)[k]);
        float a2 = ((&x2.x)[k]) + ((&yc2.x)[k]);
        float az = ((&x3.x)[k]) + ((&yc3.x)[k]);
        float ms1 = fsigmoid(a1);
        float z0  = (&zv.x)[k];
        (&zn.x)[k] = fmaf(ms1, ftanh(az) - z0, z0);
        (&g2.x)[k] = fsigmoid(a2);
    }
    ((float4*)g_Z)[i4]  = zn;
    ((float4*)g_G2)[i4] = g2;
}

__global__ void init_k()
{
    int idx = blockIdx.x * blockDim.x + threadIdx.x;
    if (idx < 8 * 32 * 4096) { g_Y[idx] = 0.0f; g_Z[idx] = 0.0f; }
}

extern "C" void kernel_launch(void* const* d_in, const int* in_sizes, int n_in,
                              void* d_out, int out_size)
{
    const float* X  = (const float*)d_in[0];
    const float* Wx = (const float*)d_in[1];
    const float* bx = (const float*)d_in[2];
    const float* Wy = (const float*)d_in[3];
    const float* by = (const float*)d_in[4];
    const float* Wz = (const float*)d_in[5];
    const float* bz = (const float*)d_in[6];
    float* out = (float*)d_out;

    static bool attr_done = false;
    if (!attr_done) {
        cudaFuncSetAttribute(conv_tc<0>, cudaFuncAttributeMaxDynamicSharedMemorySize, SMEM_SZ);
        cudaFuncSetAttribute(conv_tc<1>, cudaFuncAttributeMaxDynamicSharedMemorySize, SMEM_SZ);
        cudaFuncSetAttribute(conv_tc<2>, cudaFuncAttributeMaxDynamicSharedMemorySize, SMEM_SZ);
        attr_done = true;
    }

    // Reset recurrent state (graph is replayed; must be deterministic).
    init_k<<<(8 * 32 * 4096 + 255) / 256, 256>>>();

    // Precompute all input convolutions (tensor cores).
    conv_tc<0><<<dim3(16, 4, 400), 256, SMEM_SZ>>>(X, Wx, bx, nullptr, 0);

    // Recurrence: 50 steps, 3 launches each (all tensor-core convs).
    for (int t = 0; t < Tn; t++) {
        conv_tc<1><<<dim3(16, 3, 8), 256, SMEM_SZ>>>(nullptr, Wy, by, nullptr, t);
        elemZ_k<<<((8 * 32 * 4096) / 4 + 255) / 256, 256>>>(t);
        conv_tc<2><<<dim3(16, 1, 8), 256, SMEM_SZ>>>(nullptr, Wz, bz, out, t);
    }
}